// round 11
// baseline (speedup 1.0000x reference)
#include <cuda_runtime.h>
#include <cstdint>

#define PVOL   29791
#define MROWS  119164
#define D1     512
#define KK     128
#define BM     128
#define BN     64
#define NCOL   8
#define NT     256

// smem float offsets
#define F_AHI   0                    // 128*128
#define F_ALO   16384
#define F_BHI   32768                // 64*128
#define F_BLO   40960
#define F_YSQP  49152                // 2*128
#define F_YSQ   49408                // 128
#define F_WSQ   49536                // 64
#define SMEM_FLOATS 49600            // 198,400 bytes

__device__ __forceinline__ int idxA(int m, int k) { return m * 128 + (k ^ ((m & 7) << 2)); }
__device__ __forceinline__ int idxB(int n, int k) { return n * 128 + (k ^ ((n & 7) << 2)); }
__device__ __forceinline__ int idxS(int c, int m) { return c * 128 + (m ^ ((c & 7) << 2)); }

__device__ __forceinline__ uint32_t s2u(const void* p) {
    uint32_t a;
    asm("{ .reg .u64 t; cvta.to.shared.u64 t, %1; cvt.u32.u64 %0, t; }" : "=r"(a) : "l"(p));
    return a;
}
__device__ __forceinline__ uint32_t tf32of(float v) {
    uint32_t r;
    asm("cvt.rna.tf32.f32 %0, %1;" : "=r"(r) : "f"(v));
    return r;
}
__device__ __forceinline__ void ldsm4(uint32_t& r0, uint32_t& r1, uint32_t& r2, uint32_t& r3,
                                      uint32_t addr) {
    asm volatile("ldmatrix.sync.aligned.m8n8.x4.shared.b16 {%0,%1,%2,%3}, [%4];"
                 : "=r"(r0), "=r"(r1), "=r"(r2), "=r"(r3) : "r"(addr));
}
__device__ __forceinline__ void mma_tf32(float* d, const uint32_t* a, uint32_t b0, uint32_t b1) {
    asm volatile(
        "mma.sync.aligned.m16n8k8.row.col.f32.tf32.tf32.f32 "
        "{%0,%1,%2,%3}, {%4,%5,%6,%7}, {%8,%9}, {%0,%1,%2,%3};"
        : "+f"(d[0]), "+f"(d[1]), "+f"(d[2]), "+f"(d[3])
        : "r"(a[0]), "r"(a[1]), "r"(a[2]), "r"(a[3]), "r"(b0), "r"(b1));
}

// load all fragments for k-step KS: A hi/lo (2 m-frags) + B hi/lo (2 n-frags)
#define LOAD_FRAGS(KS, AH, AL, BH, BL) do {                                    \
    const uint32_t ka_ = (uint32_t)(((((KS) * 8) | kh4) ^ xorv) << 2);         \
    ldsm4(AH[0][0], AH[0][1], AH[0][2], AH[0][3], aAhi + rowA0 + ka_);         \
    ldsm4(AH[1][0], AH[1][1], AH[1][2], AH[1][3], aAhi + rowA1 + ka_);         \
    ldsm4(AL[0][0], AL[0][1], AL[0][2], AL[0][3], aAlo + rowA0 + ka_);         \
    ldsm4(AL[1][0], AL[1][1], AL[1][2], AL[1][3], aAlo + rowA1 + ka_);         \
    ldsm4(BH[0][0], BH[0][1], BH[0][2], BH[0][3], aBhi + rowB0 + ka_);         \
    ldsm4(BH[1][0], BH[1][1], BH[1][2], BH[1][3], aBhi + rowB1 + ka_);         \
    ldsm4(BL[0][0], BL[0][1], BL[0][2], BL[0][3], aBlo + rowB0 + ka_);         \
    ldsm4(BL[1][0], BL[1][1], BL[1][2], BL[1][3], aBlo + rowB1 + ka_);         \
} while (0)

// 24 HMMAs: 2 m-frags x 4 n-frags x 3 passes
#define DO_MMAS(AH, AL, BH, BL) do {                                           \
    _Pragma("unroll")                                                          \
    for (int f_ = 0; f_ < 2; ++f_) {                                           \
        _Pragma("unroll")                                                      \
        for (int u_ = 0; u_ < 2; ++u_) {                                       \
            _Pragma("unroll")                                                  \
            for (int v_ = 0; v_ < 2; ++v_) {                                   \
                float* ac_ = acc[f_][u_ * 2 + v_];                             \
                mma_tf32(ac_, AH[f_], BH[u_][v_], BH[u_][2 + v_]);             \
                mma_tf32(ac_, AH[f_], BL[u_][v_], BL[u_][2 + v_]);             \
                mma_tf32(ac_, AL[f_], BH[u_][v_], BH[u_][2 + v_]);             \
            }                                                                  \
        }                                                                      \
    }                                                                          \
} while (0)

__global__ __launch_bounds__(NT, 1)
void gk_kernel(const float* __restrict__ x, const float* __restrict__ w,
               float* __restrict__ out) {
    extern __shared__ float sm[];
    uint32_t* sAhi = (uint32_t*)(sm + F_AHI);
    uint32_t* sAlo = (uint32_t*)(sm + F_ALO);
    uint32_t* sBhi = (uint32_t*)(sm + F_BHI);
    uint32_t* sBlo = (uint32_t*)(sm + F_BLO);
    float*    st   = sm + F_BHI;          // stage reuses Bhi after mma reads
    float*    ysqp = sm + F_YSQP;
    float*    ysq  = sm + F_YSQ;
    float*    wsq  = sm + F_WSQ;

    const uint32_t aAhi = s2u(sAhi);
    const uint32_t aAlo = s2u(sAlo);
    const uint32_t aBhi = s2u(sBhi);
    const uint32_t aBlo = s2u(sBlo);

    const int tid  = threadIdx.x;
    const int wid  = tid >> 5;
    const int lane = tid & 31;
    const int row0 = blockIdx.x * BM;

    // ---------------- gather A -> hi/lo tf32 (swizzled) + ||y||^2 -----------
    {
        const int m    = tid & 127;
        const int half = tid >> 7;           // kw bit
        const int row  = row0 + m;
        float s = 0.0f;
        if (row < MROWS) {
            const int n   = row / PVOL;
            const int p   = row - n * PVOL;
            const int d   = p / 961;
            const int rem = p - d * 961;
            const int h   = rem / 31;
            const int wx  = rem - h * 31;
            const long base = (long)n * 524288 + d * 1024 + h * 32 + wx + half;
            #pragma unroll 4
            for (int it = 0; it < 64; ++it) {
                const int c  = it >> 2;
                const int kd = (it >> 1) & 1;
                const int kh = it & 1;
                const int k  = c * 8 + kd * 4 + kh * 2 + half;
                const float v = x[base + (long)c * 32768 + kd * 1024 + kh * 32];
                const uint32_t hib = tf32of(v);
                const float lo = v - __uint_as_float(hib);
                const int o = idxA(m, k);
                sAhi[o] = hib;
                sAlo[o] = tf32of(lo);
                s = fmaf(v, v, s);
            }
        } else {
            #pragma unroll 4
            for (int it = 0; it < 64; ++it) {
                const int k = (it >> 2) * 8 + (((it >> 1) & 1) << 2) + ((it & 1) << 1) + half;
                const int o = idxA(m, k);
                sAhi[o] = 0u;
                sAlo[o] = 0u;
            }
        }
        ysqp[half * 128 + m] = s;
    }
    __syncthreads();
    if (tid < 128) ysq[tid] = ysqp[tid] + ysqp[128 + tid];

    // ---- per-warp fragment geometry: warp tile 32(m) x 32(n) ----
    const int m0 = (wid & 3) * 32;       // 4 warps over M=128
    const int n0 = (wid >> 2) * 32;      // 2 warps over N=64
    const int r    = lane & 7;
    const int midx = lane >> 3;
    const int kh4  = (midx >> 1) * 4;
    const int xorv = r << 2;
    const uint32_t rowA0 = (uint32_t)(m0 + (midx & 1) * 8 + r) * 512u;
    const uint32_t rowA1 = rowA0 + 16u * 512u;
    const uint32_t rowB0 = (uint32_t)(n0 + (midx & 1) * 8 + r) * 512u;
    const uint32_t rowB1 = rowB0 + 16u * 512u;

    const int c  = lane & 3;
    const int rg = lane >> 2;

    for (int iter = 0; iter < NCOL; ++iter) {
        const int col0 = iter * BN;

        // ------------- fill B hi/lo (STS.128) + ||w||^2 via shfl ------------
        {
            const int cg  = lane >> 2;          // 8 cols per warp
            const int sub = lane & 3;           // 32-k chunk
            const int nn  = wid * 8 + cg;       // 0..63
            const float* wr = w + (long)(col0 + nn) * KK + sub * 32;
            float s = 0.0f;
            #pragma unroll
            for (int j = 0; j < 8; ++j) {
                const float4 v4 = *(const float4*)(wr + j * 4);
                uint4 h4, l4;
                h4.x = tf32of(v4.x); l4.x = tf32of(v4.x - __uint_as_float(h4.x));
                h4.y = tf32of(v4.y); l4.y = tf32of(v4.y - __uint_as_float(h4.y));
                h4.z = tf32of(v4.z); l4.z = tf32of(v4.z - __uint_as_float(h4.z));
                h4.w = tf32of(v4.w); l4.w = tf32of(v4.w - __uint_as_float(h4.w));
                const int o = idxB(nn, sub * 32 + j * 4);
                *(uint4*)&sBhi[o] = h4;
                *(uint4*)&sBlo[o] = l4;
                s = fmaf(v4.x, v4.x, s);
                s = fmaf(v4.y, v4.y, s);
                s = fmaf(v4.z, v4.z, s);
                s = fmaf(v4.w, v4.w, s);
            }
            s += __shfl_xor_sync(0xFFFFFFFFu, s, 2);
            s += __shfl_xor_sync(0xFFFFFFFFu, s, 1);
            if (sub == 0) wsq[nn] = s;
        }
        __syncthreads();

        // ------------- tensor GEMM: 3-pass tf32, prefetched fragments --------
        float acc[2][4][4];
        #pragma unroll
        for (int f = 0; f < 2; ++f)
            #pragma unroll
            for (int g = 0; g < 4; ++g)
                #pragma unroll
                for (int e = 0; e < 4; ++e) acc[f][g][e] = 0.0f;

        uint32_t ah0[2][4], al0[2][4], bh0[2][4], bl0[2][4];
        uint32_t ah1[2][4], al1[2][4], bh1[2][4], bl1[2][4];
        LOAD_FRAGS(0, ah0, al0, bh0, bl0);
        #pragma unroll
        for (int ks = 0; ks < 16; ks += 2) {
            LOAD_FRAGS(ks + 1, ah1, al1, bh1, bl1);
            DO_MMAS(ah0, al0, bh0, bl0);
            if (ks + 2 < 16) LOAD_FRAGS(ks + 2, ah0, al0, bh0, bl0);
            DO_MMAS(ah1, al1, bh1, bl1);
        }
        __syncthreads();   // done reading sBhi/sBlo; stage overwrites Bhi

        // ------------- epilogue: exp -> swizzled stage -----------------------
        #pragma unroll
        for (int f = 0; f < 2; ++f) {
            const int r0 = m0 + f * 16 + rg;
            const int r1 = r0 + 8;
            const float ys0 = ysq[r0];
            const float ys1 = ysq[r1];
            #pragma unroll
            for (int g = 0; g < 4; ++g) {
                const int cb = n0 + g * 8 + 2 * c;
                const float ws0 = wsq[cb];
                const float ws1 = wsq[cb + 1];
                st[idxS(cb,     r0)] = __expf(fmaf(2.0f, acc[f][g][0], -(ys0 + ws0)));
                st[idxS(cb + 1, r0)] = __expf(fmaf(2.0f, acc[f][g][1], -(ys0 + ws1)));
                st[idxS(cb,     r1)] = __expf(fmaf(2.0f, acc[f][g][2], -(ys1 + ws0)));
                st[idxS(cb + 1, r1)] = __expf(fmaf(2.0f, acc[f][g][3], -(ys1 + ws1)));
            }
        }
        __syncthreads();

        // ------------- coalesced global stores -------------------------------
        #pragma unroll 4
        for (int l = 0; l < 32; ++l) {
            const int e   = tid + l * NT;
            const int col = e >> 7;            // 0..63
            const int m   = e & 127;
            const int row = row0 + m;
            if (row < MROWS) {
                const int n = row / PVOL;
                const int p = row - n * PVOL;
                out[(long)(n * D1 + col0 + col) * PVOL + p] = st[idxS(col, m)];
            }
        }
        __syncthreads();   // protect Bhi(stage)/Blo before next fill
    }
}

extern "C" void kernel_launch(void* const* d_in, const int* in_sizes, int n_in,
                              void* d_out, int out_size) {
    const float* x = (const float*)d_in[0];
    const float* w = (const float*)d_in[1];
    float* out = (float*)d_out;

    const int smem_bytes = SMEM_FLOATS * (int)sizeof(float);  // 198,400
    cudaFuncSetAttribute(gk_kernel, cudaFuncAttributeMaxDynamicSharedMemorySize,
                         smem_bytes);
    dim3 grid((MROWS + BM - 1) / BM, 1);   // 931
    gk_kernel<<<grid, NT, smem_bytes>>>(x, w, out);
}

// round 12
// speedup vs baseline: 1.6325x; 1.6325x over previous
#include <cuda_runtime.h>
#include <cuda_bf16.h>
#include <cstdint>

#define PVOL   29791
#define MROWS  119164
#define D1     512
#define KK     128
#define BM     128
#define BN     64
#define NCOL   8
#define NT     256

// smem byte offsets
#define O_A0    0          // 128x128 bf16 = 32768
#define O_A1    32768
#define O_B0    65536      // 64x128 bf16 = 16384
#define O_B1    81920
#define O_ST    65536      // stage 128x64 f32 = 32768 (reuses B0+B1)
#define O_YSQP  98304      // 2*128 f32
#define O_YSQ   99328      // 128 f32
#define O_WSQ   99840      // 64 f32
#define SMEM_BYTES 100096

// bf16 element index with 16B-chunk XOR swizzle (row&7)
__device__ __forceinline__ int idx16(int row, int k) {
    return row * 128 + ((((k >> 3) ^ (row & 7))) << 3) + (k & 7);
}

__device__ __forceinline__ uint32_t s2u(const void* p) {
    uint32_t a;
    asm("{ .reg .u64 t; cvta.to.shared.u64 t, %1; cvt.u32.u64 %0, t; }" : "=r"(a) : "l"(p));
    return a;
}
__device__ __forceinline__ void ldsm4(uint32_t& r0, uint32_t& r1, uint32_t& r2, uint32_t& r3,
                                      uint32_t addr) {
    asm volatile("ldmatrix.sync.aligned.m8n8.x4.shared.b16 {%0,%1,%2,%3}, [%4];"
                 : "=r"(r0), "=r"(r1), "=r"(r2), "=r"(r3) : "r"(addr));
}
__device__ __forceinline__ void mma_bf16(float* d, const uint32_t* a, uint32_t b0, uint32_t b1) {
    asm volatile(
        "mma.sync.aligned.m16n8k16.row.col.f32.bf16.bf16.f32 "
        "{%0,%1,%2,%3}, {%4,%5,%6,%7}, {%8,%9}, {%0,%1,%2,%3};"
        : "+f"(d[0]), "+f"(d[1]), "+f"(d[2]), "+f"(d[3])
        : "r"(a[0]), "r"(a[1]), "r"(a[2]), "r"(a[3]), "r"(b0), "r"(b1));
}
__device__ __forceinline__ unsigned short bfbits(float v) {
    return __bfloat16_as_ushort(__float2bfloat16(v));
}

__global__ __launch_bounds__(NT, 2)
void gk_kernel(const float* __restrict__ x, const float* __restrict__ w,
               float* __restrict__ out) {
    extern __shared__ __align__(16) char smem[];
    uint16_t* sA0 = (uint16_t*)(smem + O_A0);
    uint16_t* sA1 = (uint16_t*)(smem + O_A1);
    float*    st  = (float*)(smem + O_ST);
    float*    ysqp = (float*)(smem + O_YSQP);
    float*    ysq  = (float*)(smem + O_YSQ);
    float*    wsq  = (float*)(smem + O_WSQ);

    const uint32_t aA0 = s2u(smem + O_A0);
    const uint32_t aA1 = s2u(smem + O_A1);
    const uint32_t aB0 = s2u(smem + O_B0);
    const uint32_t aB1 = s2u(smem + O_B1);

    const int tid  = threadIdx.x;
    const int wid  = tid >> 5;
    const int lane = tid & 31;
    const int row0 = blockIdx.x * BM;

    // ---------------- gather A -> 2-term bf16 tiles + ||y||^2 ----------------
    {
        const int m    = tid & 127;
        const int half = tid >> 7;           // kw bit
        const int row  = row0 + m;
        float s = 0.0f;
        if (row < MROWS) {
            const int n   = row / PVOL;
            const int p   = row - n * PVOL;
            const int d   = p / 961;
            const int rem = p - d * 961;
            const int h   = rem / 31;
            const int wx  = rem - h * 31;
            const long base = (long)n * 524288 + d * 1024 + h * 32 + wx + half;
            #pragma unroll 4
            for (int it = 0; it < 64; ++it) {
                const int c  = it >> 2;
                const int kd = (it >> 1) & 1;
                const int kh = it & 1;
                const int k  = c * 8 + kd * 4 + kh * 2 + half;
                const float v = x[base + (long)c * 32768 + kd * 1024 + kh * 32];
                const unsigned short u0 = bfbits(v);
                __nv_bfloat16_raw raw; raw.x = u0;
                const float f0 = __bfloat162float(*(__nv_bfloat16*)&raw);
                const unsigned short u1 = bfbits(v - f0);
                const int o = idx16(m, k);
                sA0[o] = u0;
                sA1[o] = u1;
                s = fmaf(v, v, s);
            }
        } else {
            #pragma unroll 4
            for (int it = 0; it < 64; ++it) {
                const int k = (it >> 2) * 8 + (((it >> 1) & 1) << 2) + ((it & 1) << 1) + half;
                const int o = idx16(m, k);
                sA0[o] = 0;
                sA1[o] = 0;
            }
        }
        ysqp[half * 128 + m] = s;
    }
    __syncthreads();
    if (tid < 128) ysq[tid] = ysqp[tid] + ysqp[128 + tid];

    // ---- per-warp fragment geometry: warp tile 32(m) x 32(n) ----
    const int m0 = (wid & 3) * 32;
    const int n0 = (wid >> 2) * 32;
    const int r    = lane & 7;
    const int midx = lane >> 3;
    const int mi1  = (midx & 1) * 8;
    const int kmi  = midx >> 1;
    const uint32_t rowA0 = (uint32_t)(m0 + mi1 + r) * 256u;   // bytes (256B rows)
    const uint32_t rowA1 = rowA0 + 16u * 256u;
    const uint32_t rowB0 = (uint32_t)(n0 + mi1 + r) * 256u;
    const uint32_t rowB1 = rowB0 + 16u * 256u;

    const int c  = lane & 3;
    const int rg = lane >> 2;

    for (int iter = 0; iter < NCOL; ++iter) {
        const int col0 = iter * BN;

        // ------------- fill B (2-term bf16, STS.128) + ||w||^2 --------------
        {
            const int cg  = lane >> 2;          // 8 cols per warp
            const int sub = lane & 3;           // 32-k chunk
            const int nn  = wid * 8 + cg;       // 0..63
            const float* wr = w + (long)(col0 + nn) * KK + sub * 32;
            float s = 0.0f;
            #pragma unroll
            for (int j = 0; j < 4; ++j) {
                const float4 va = *(const float4*)(wr + j * 8);
                const float4 vb = *(const float4*)(wr + j * 8 + 4);
                const float f[8] = {va.x, va.y, va.z, va.w, vb.x, vb.y, vb.z, vb.w};
                uint32_t h[4], l[4];
                #pragma unroll
                for (int q = 0; q < 4; ++q) {
                    const unsigned short h0 = bfbits(f[2 * q]);
                    const unsigned short h1 = bfbits(f[2 * q + 1]);
                    __nv_bfloat16_raw r0; r0.x = h0;
                    __nv_bfloat16_raw r1; r1.x = h1;
                    const float g0 = __bfloat162float(*(__nv_bfloat16*)&r0);
                    const float g1 = __bfloat162float(*(__nv_bfloat16*)&r1);
                    const unsigned short l0 = bfbits(f[2 * q] - g0);
                    const unsigned short l1 = bfbits(f[2 * q + 1] - g1);
                    h[q] = (uint32_t)h0 | ((uint32_t)h1 << 16);
                    l[q] = (uint32_t)l0 | ((uint32_t)l1 << 16);
                    s = fmaf(f[2 * q], f[2 * q], s);
                    s = fmaf(f[2 * q + 1], f[2 * q + 1], s);
                }
                const int choff = ((((sub << 2) + j) ^ (nn & 7)) << 4);
                *(uint4*)(smem + O_B0 + nn * 256 + choff) = make_uint4(h[0], h[1], h[2], h[3]);
                *(uint4*)(smem + O_B1 + nn * 256 + choff) = make_uint4(l[0], l[1], l[2], l[3]);
            }
            s += __shfl_xor_sync(0xFFFFFFFFu, s, 2);
            s += __shfl_xor_sync(0xFFFFFFFFu, s, 1);
            if (sub == 0) wsq[nn] = s;
        }
        __syncthreads();

        // ------------- tensor GEMM: 4-pass bf16 m16n8k16 ---------------------
        float acc[2][4][4];
        #pragma unroll
        for (int f = 0; f < 2; ++f)
            #pragma unroll
            for (int g = 0; g < 4; ++g)
                #pragma unroll
                for (int e = 0; e < 4; ++e) acc[f][g][e] = 0.0f;

        #pragma unroll
        for (int ks = 0; ks < 8; ++ks) {
            const uint32_t choff = (uint32_t)((((ks * 2 + kmi) ^ r)) << 4);
            uint32_t A0[2][4], A1[2][4], B0[2][4], B1[2][4];
            ldsm4(A0[0][0], A0[0][1], A0[0][2], A0[0][3], aA0 + rowA0 + choff);
            ldsm4(A0[1][0], A0[1][1], A0[1][2], A0[1][3], aA0 + rowA1 + choff);
            ldsm4(A1[0][0], A1[0][1], A1[0][2], A1[0][3], aA1 + rowA0 + choff);
            ldsm4(A1[1][0], A1[1][1], A1[1][2], A1[1][3], aA1 + rowA1 + choff);
            ldsm4(B0[0][0], B0[0][1], B0[0][2], B0[0][3], aB0 + rowB0 + choff);
            ldsm4(B0[1][0], B0[1][1], B0[1][2], B0[1][3], aB0 + rowB1 + choff);
            ldsm4(B1[0][0], B1[0][1], B1[0][2], B1[0][3], aB1 + rowB0 + choff);
            ldsm4(B1[1][0], B1[1][1], B1[1][2], B1[1][3], aB1 + rowB1 + choff);

            #pragma unroll
            for (int f = 0; f < 2; ++f)
                #pragma unroll
                for (int u = 0; u < 2; ++u)
                    #pragma unroll
                    for (int v = 0; v < 2; ++v) {
                        float* ac = acc[f][u * 2 + v];
                        mma_bf16(ac, A0[f], B0[u][v], B0[u][2 + v]);
                        mma_bf16(ac, A0[f], B1[u][v], B1[u][2 + v]);
                        mma_bf16(ac, A1[f], B0[u][v], B0[u][2 + v]);
                        mma_bf16(ac, A1[f], B1[u][v], B1[u][2 + v]);
                    }
        }
        __syncthreads();   // done reading B tiles; stage overwrites them

        // ------------- epilogue: exp -> swizzled fp32 stage ------------------
        #pragma unroll
        for (int f = 0; f < 2; ++f) {
            const int r0 = m0 + f * 16 + rg;
            const int r1 = r0 + 8;
            const float ys0 = ysq[r0];
            const float ys1 = ysq[r1];
            #pragma unroll
            for (int u = 0; u < 2; ++u)
                #pragma unroll
                for (int v = 0; v < 2; ++v) {
                    const float* ac = acc[f][u * 2 + v];
                    const int cb = n0 + u * 16 + v * 8 + 2 * c;
                    const float ws0 = wsq[cb];
                    const float ws1 = wsq[cb + 1];
                    // stage idx: col*128 + (m ^ ((col&7)<<2))  (fp32 swizzle)
                    st[cb * 128 + (r0 ^ ((cb & 7) << 2))]       = __expf(fmaf(2.0f, ac[0], -(ys0 + ws0)));
                    st[(cb + 1) * 128 + (r0 ^ (((cb + 1) & 7) << 2))] = __expf(fmaf(2.0f, ac[1], -(ys0 + ws1)));
                    st[cb * 128 + (r1 ^ ((cb & 7) << 2))]       = __expf(fmaf(2.0f, ac[2], -(ys1 + ws0)));
                    st[(cb + 1) * 128 + (r1 ^ (((cb + 1) & 7) << 2))] = __expf(fmaf(2.0f, ac[3], -(ys1 + ws1)));
                }
        }
        __syncthreads();

        // ------------- coalesced global stores -------------------------------
        #pragma unroll 4
        for (int l = 0; l < 32; ++l) {
            const int e   = tid + l * NT;
            const int col = e >> 7;            // 0..63
            const int m   = e & 127;
            const int row = row0 + m;
            if (row < MROWS) {
                const int n = row / PVOL;
                const int p = row - n * PVOL;
                out[(long)(n * D1 + col0 + col) * PVOL + p] =
                    st[col * 128 + (m ^ ((col & 7) << 2))];
            }
        }
        __syncthreads();   // protect B(stage) before next fill
    }
}

extern "C" void kernel_launch(void* const* d_in, const int* in_sizes, int n_in,
                              void* d_out, int out_size) {
    const float* x = (const float*)d_in[0];
    const float* w = (const float*)d_in[1];
    float* out = (float*)d_out;

    cudaFuncSetAttribute(gk_kernel, cudaFuncAttributeMaxDynamicSharedMemorySize,
                         SMEM_BYTES);
    dim3 grid((MROWS + BM - 1) / BM, 1);   // 931
    gk_kernel<<<grid, NT, SMEM_BYTES>>>(x, w, out);
}

// round 14
// speedup vs baseline: 1.8030x; 1.1044x over previous
#include <cuda_runtime.h>
#include <cuda_bf16.h>
#include <cstdint>

#define PVOL   29791
#define MROWS  119164
#define D1     512
#define KK     128
#define BM     128
#define BN     64
#define NCOL   8
#define NT     256

// smem byte offsets
#define O_A0    0          // 128x128 bf16 = 32768
#define O_A1    32768
#define O_B0    65536      // 64x128 bf16 = 16384
#define O_B1    81920
#define O_ST    65536      // stage 64x128 f32 = 32768 (reuses B0+B1)
#define O_YSQP  98304      // 2*128 f32
#define O_YSQ   99328      // 128 f32
#define O_WSQ   99840      // 64 f32
#define SMEM_BYTES 100096

// bf16 element index with 16B-chunk XOR swizzle (row&7)
__device__ __forceinline__ int idx16(int row, int k) {
    return row * 128 + ((((k >> 3) ^ (row & 7))) << 3) + (k & 7);
}

__device__ __forceinline__ uint32_t s2u(const void* p) {
    uint32_t a;
    asm("{ .reg .u64 t; cvta.to.shared.u64 t, %1; cvt.u32.u64 %0, t; }" : "=r"(a) : "l"(p));
    return a;
}
__device__ __forceinline__ void ldsm4(uint32_t& r0, uint32_t& r1, uint32_t& r2, uint32_t& r3,
                                      uint32_t addr) {
    asm volatile("ldmatrix.sync.aligned.m8n8.x4.shared.b16 {%0,%1,%2,%3}, [%4];"
                 : "=r"(r0), "=r"(r1), "=r"(r2), "=r"(r3) : "r"(addr));
}
__device__ __forceinline__ void mma_bf16(float* d, const uint32_t* a, uint32_t b0, uint32_t b1) {
    asm volatile(
        "mma.sync.aligned.m16n8k16.row.col.f32.bf16.bf16.f32 "
        "{%0,%1,%2,%3}, {%4,%5,%6,%7}, {%8,%9}, {%0,%1,%2,%3};"
        : "+f"(d[0]), "+f"(d[1]), "+f"(d[2]), "+f"(d[3])
        : "r"(a[0]), "r"(a[1]), "r"(a[2]), "r"(a[3]), "r"(b0), "r"(b1));
}
__device__ __forceinline__ unsigned short bfbits(float v) {
    return __bfloat16_as_ushort(__float2bfloat16(v));
}

__global__ __launch_bounds__(NT, 2)
void gk_kernel(const float* __restrict__ x, const float* __restrict__ w,
               float* __restrict__ out) {
    extern __shared__ __align__(16) char smem[];
    uint16_t* sA0 = (uint16_t*)(smem + O_A0);
    uint16_t* sA1 = (uint16_t*)(smem + O_A1);
    float*    st  = (float*)(smem + O_ST);
    float*    ysqp = (float*)(smem + O_YSQP);
    float*    ysq  = (float*)(smem + O_YSQ);
    float*    wsq  = (float*)(smem + O_WSQ);

    const uint32_t aA0 = s2u(smem + O_A0);
    const uint32_t aA1 = s2u(smem + O_A1);
    const uint32_t aB0 = s2u(smem + O_B0);
    const uint32_t aB1 = s2u(smem + O_B1);

    const int tid  = threadIdx.x;
    const int wid  = tid >> 5;
    const int lane = tid & 31;
    const int row0 = blockIdx.x * BM;

    // ---- per-thread output coordinates (hoisted: one divide per thread) ----
    const int mT   = tid & 127;
    const int hT   = tid >> 7;           // which half of cols this thread stores
    const int rowT = row0 + mT;
    int nT = 0, pT = 0;
    if (rowT < MROWS) { nT = rowT / PVOL; pT = rowT - nT * PVOL; }

    // ---------------- gather A -> 2-term bf16 tiles + ||y||^2 ----------------
    {
        const int m    = mT;
        const int half = hT;             // kw bit
        float s = 0.0f;
        if (rowT < MROWS) {
            const int d   = pT / 961;
            const int rem = pT - d * 961;
            const int h   = rem / 31;
            const int wx  = rem - h * 31;
            const long base = (long)nT * 524288 + d * 1024 + h * 32 + wx + half;
            #pragma unroll 4
            for (int it = 0; it < 64; ++it) {
                const int c  = it >> 2;
                const int kd = (it >> 1) & 1;
                const int kh = it & 1;
                const int k  = c * 8 + kd * 4 + kh * 2 + half;
                const float v = x[base + (long)c * 32768 + kd * 1024 + kh * 32];
                const unsigned short u0 = bfbits(v);
                __nv_bfloat16_raw raw; raw.x = u0;
                const float f0 = __bfloat162float(*(__nv_bfloat16*)&raw);
                const unsigned short u1 = bfbits(v - f0);
                const int o = idx16(m, k);
                sA0[o] = u0;
                sA1[o] = u1;
                s = fmaf(v, v, s);
            }
        } else {
            #pragma unroll 4
            for (int it = 0; it < 64; ++it) {
                const int k = (it >> 2) * 8 + (((it >> 1) & 1) << 2) + ((it & 1) << 1) + half;
                const int o = idx16(m, k);
                sA0[o] = 0;
                sA1[o] = 0;
            }
        }
        ysqp[half * 128 + m] = s;
    }
    __syncthreads();
    if (tid < 128) ysq[tid] = ysqp[tid] + ysqp[128 + tid];

    // ---- per-warp fragment geometry: warp tile 32(m) x 32(n) ----
    const int m0 = (wid & 3) * 32;
    const int n0 = (wid >> 2) * 32;
    const int r    = lane & 7;
    const int midx = lane >> 3;
    const int mi1  = (midx & 1) * 8;
    const int kmi  = midx >> 1;
    const uint32_t rowA0 = (uint32_t)(m0 + mi1 + r) * 256u;   // bytes (256B rows)
    const uint32_t rowA1 = rowA0 + 16u * 256u;
    const uint32_t rowB0 = (uint32_t)(n0 + mi1 + r) * 256u;
    const uint32_t rowB1 = rowB0 + 16u * 256u;

    const int c  = lane & 3;
    const int rg = lane >> 2;

    for (int iter = 0; iter < NCOL; ++iter) {
        const int col0 = iter * BN;

        // ------------- fill B (2-term bf16, STS.128) + ||w||^2 --------------
        {
            const int cg  = lane >> 2;          // 8 cols per warp
            const int sub = lane & 3;           // 32-k chunk
            const int nn  = wid * 8 + cg;       // 0..63
            const float* wr = w + (long)(col0 + nn) * KK + sub * 32;
            float s = 0.0f;
            #pragma unroll
            for (int j = 0; j < 4; ++j) {
                const float4 va = *(const float4*)(wr + j * 8);
                const float4 vb = *(const float4*)(wr + j * 8 + 4);
                const float f[8] = {va.x, va.y, va.z, va.w, vb.x, vb.y, vb.z, vb.w};
                uint32_t h[4], l[4];
                #pragma unroll
                for (int q = 0; q < 4; ++q) {
                    const unsigned short h0 = bfbits(f[2 * q]);
                    const unsigned short h1 = bfbits(f[2 * q + 1]);
                    __nv_bfloat16_raw r0; r0.x = h0;
                    __nv_bfloat16_raw r1; r1.x = h1;
                    const float g0 = __bfloat162float(*(__nv_bfloat16*)&r0);
                    const float g1 = __bfloat162float(*(__nv_bfloat16*)&r1);
                    const unsigned short l0 = bfbits(f[2 * q] - g0);
                    const unsigned short l1 = bfbits(f[2 * q + 1] - g1);
                    h[q] = (uint32_t)h0 | ((uint32_t)h1 << 16);
                    l[q] = (uint32_t)l0 | ((uint32_t)l1 << 16);
                    s = fmaf(f[2 * q], f[2 * q], s);
                    s = fmaf(f[2 * q + 1], f[2 * q + 1], s);
                }
                const int choff = ((((sub << 2) + j) ^ (nn & 7)) << 4);
                *(uint4*)(smem + O_B0 + nn * 256 + choff) = make_uint4(h[0], h[1], h[2], h[3]);
                *(uint4*)(smem + O_B1 + nn * 256 + choff) = make_uint4(l[0], l[1], l[2], l[3]);
            }
            s += __shfl_xor_sync(0xFFFFFFFFu, s, 2);
            s += __shfl_xor_sync(0xFFFFFFFFu, s, 1);
            if (sub == 0) wsq[nn] = s;
        }
        __syncthreads();

        // ------------- tensor GEMM: 3-pass bf16 m16n8k16 ---------------------
        float acc[2][4][4];
        #pragma unroll
        for (int f = 0; f < 2; ++f)
            #pragma unroll
            for (int g = 0; g < 4; ++g)
                #pragma unroll
                for (int e = 0; e < 4; ++e) acc[f][g][e] = 0.0f;

        #pragma unroll
        for (int ks = 0; ks < 8; ++ks) {
            const uint32_t choff = (uint32_t)((((ks * 2 + kmi) ^ r)) << 4);
            uint32_t A0[2][4], A1[2][4], B0[2][4], B1[2][4];
            ldsm4(A0[0][0], A0[0][1], A0[0][2], A0[0][3], aA0 + rowA0 + choff);
            ldsm4(A0[1][0], A0[1][1], A0[1][2], A0[1][3], aA0 + rowA1 + choff);
            ldsm4(A1[0][0], A1[0][1], A1[0][2], A1[0][3], aA1 + rowA0 + choff);
            ldsm4(A1[1][0], A1[1][1], A1[1][2], A1[1][3], aA1 + rowA1 + choff);
            ldsm4(B0[0][0], B0[0][1], B0[0][2], B0[0][3], aB0 + rowB0 + choff);
            ldsm4(B0[1][0], B0[1][1], B0[1][2], B0[1][3], aB0 + rowB1 + choff);
            ldsm4(B1[0][0], B1[0][1], B1[0][2], B1[0][3], aB1 + rowB0 + choff);
            ldsm4(B1[1][0], B1[1][1], B1[1][2], B1[1][3], aB1 + rowB1 + choff);

            #pragma unroll
            for (int f = 0; f < 2; ++f)
                #pragma unroll
                for (int u = 0; u < 2; ++u)
                    #pragma unroll
                    for (int v = 0; v < 2; ++v) {
                        float* ac = acc[f][u * 2 + v];
                        mma_bf16(ac, A0[f], B0[u][v], B0[u][2 + v]);
                        mma_bf16(ac, A0[f], B1[u][v], B1[u][2 + v]);
                        mma_bf16(ac, A1[f], B0[u][v], B0[u][2 + v]);
                        // A1*B1 dropped: |a1*b1| <= 2^-18 |y||w| — negligible
                    }
        }
        __syncthreads();   // done reading B tiles; stage overwrites them

        // ------------- epilogue: exp -> swizzled fp32 stage ------------------
        #pragma unroll
        for (int f = 0; f < 2; ++f) {
            const int r0 = m0 + f * 16 + rg;
            const int r1 = r0 + 8;
            const float ys0 = ysq[r0];
            const float ys1 = ysq[r1];
            #pragma unroll
            for (int u = 0; u < 2; ++u)
                #pragma unroll
                for (int v = 0; v < 2; ++v) {
                    const float* ac = acc[f][u * 2 + v];
                    const int cb = n0 + u * 16 + v * 8 + 2 * c;
                    const float ws0 = wsq[cb];
                    const float ws1 = wsq[cb + 1];
                    st[cb * 128 + (r0 ^ ((cb & 7) << 2))]             = __expf(fmaf(2.0f, ac[0], -(ys0 + ws0)));
                    st[(cb + 1) * 128 + (r0 ^ (((cb + 1) & 7) << 2))] = __expf(fmaf(2.0f, ac[1], -(ys0 + ws1)));
                    st[cb * 128 + (r1 ^ ((cb & 7) << 2))]             = __expf(fmaf(2.0f, ac[2], -(ys1 + ws0)));
                    st[(cb + 1) * 128 + (r1 ^ (((cb + 1) & 7) << 2))] = __expf(fmaf(2.0f, ac[3], -(ys1 + ws1)));
                }
        }
        __syncthreads();

        // ------------- coalesced stores: fixed row per thread ----------------
        // thread owns row rowT; cols col0 + (l*2 + hT): one divide total,
        // lanes span consecutive m -> consecutive p -> coalesced STG.32.
        if (rowT < MROWS) {
            float* ob = out + (long)(nT * D1 + col0) * PVOL + pT;
            #pragma unroll
            for (int l = 0; l < 32; ++l) {
                const int col = l * 2 + hT;
                ob[(long)col * PVOL] = st[col * 128 + (mT ^ ((col & 7) << 2))];
            }
        }
        __syncthreads();   // protect B(stage) before next fill
    }
}

extern "C" void kernel_launch(void* const* d_in, const int* in_sizes, int n_in,
                              void* d_out, int out_size) {
    const float* x = (const float*)d_in[0];
    const float* w = (const float*)d_in[1];
    float* out = (float*)d_out;

    cudaFuncSetAttribute(gk_kernel, cudaFuncAttributeMaxDynamicSharedMemorySize,
                         SMEM_BYTES);
    dim3 grid((MROWS + BM - 1) / BM, 1);   // 931
    gk_kernel<<<grid, NT, SMEM_BYTES>>>(x, w, out);
}

// round 15
// speedup vs baseline: 1.8593x; 1.0312x over previous
#include <cuda_runtime.h>
#include <cuda_bf16.h>
#include <cstdint>

#define PVOL   29791
#define MROWS  119164
#define D1     512
#define KK     128
#define BM     128
#define BN     64
#define NCOL   8
#define NT     256

// smem byte offsets
#define O_A0    0          // 128x128 bf16 = 32768
#define O_A1    32768
#define O_B0    65536      // 64x128 bf16 = 16384
#define O_B1    81920
#define O_YSQP  98304      // 2*128 f32
#define O_YSQ   99328      // 128 f32
#define O_WSQ   99840      // 64 f32
#define SMEM_BYTES 100096

// bf16 element index with 16B-chunk XOR swizzle (row&7)
__device__ __forceinline__ int idx16(int row, int k) {
    return row * 128 + ((((k >> 3) ^ (row & 7))) << 3) + (k & 7);
}

__device__ __forceinline__ uint32_t s2u(const void* p) {
    uint32_t a;
    asm("{ .reg .u64 t; cvta.to.shared.u64 t, %1; cvt.u32.u64 %0, t; }" : "=r"(a) : "l"(p));
    return a;
}
__device__ __forceinline__ void ldsm4(uint32_t& r0, uint32_t& r1, uint32_t& r2, uint32_t& r3,
                                      uint32_t addr) {
    asm volatile("ldmatrix.sync.aligned.m8n8.x4.shared.b16 {%0,%1,%2,%3}, [%4];"
                 : "=r"(r0), "=r"(r1), "=r"(r2), "=r"(r3) : "r"(addr));
}
__device__ __forceinline__ void mma_bf16(float* d, const uint32_t* a, uint32_t b0, uint32_t b1) {
    asm volatile(
        "mma.sync.aligned.m16n8k16.row.col.f32.bf16.bf16.f32 "
        "{%0,%1,%2,%3}, {%4,%5,%6,%7}, {%8,%9}, {%0,%1,%2,%3};"
        : "+f"(d[0]), "+f"(d[1]), "+f"(d[2]), "+f"(d[3])
        : "r"(a[0]), "r"(a[1]), "r"(a[2]), "r"(a[3]), "r"(b0), "r"(b1));
}
__device__ __forceinline__ unsigned short bfbits(float v) {
    return __bfloat16_as_ushort(__float2bfloat16(v));
}

__global__ __launch_bounds__(NT, 2)
void gk_kernel(const float* __restrict__ x, const float* __restrict__ w,
               float* __restrict__ out) {
    extern __shared__ __align__(16) char smem[];
    uint16_t* sA0 = (uint16_t*)(smem + O_A0);
    uint16_t* sA1 = (uint16_t*)(smem + O_A1);
    float*    ysqp = (float*)(smem + O_YSQP);
    float*    ysq  = (float*)(smem + O_YSQ);
    float*    wsq  = (float*)(smem + O_WSQ);

    const uint32_t aA0 = s2u(smem + O_A0);
    const uint32_t aA1 = s2u(smem + O_A1);
    const uint32_t aB0 = s2u(smem + O_B0);
    const uint32_t aB1 = s2u(smem + O_B1);

    const int tid  = threadIdx.x;
    const int wid  = tid >> 5;
    const int lane = tid & 31;
    const int row0 = blockIdx.x * BM;

    // ---------------- gather A -> 2-term bf16 tiles + ||y||^2 ----------------
    {
        const int m    = tid & 127;
        const int half = tid >> 7;           // kw bit
        const int row  = row0 + m;
        float s = 0.0f;
        if (row < MROWS) {
            const int n   = row / PVOL;
            const int p   = row - n * PVOL;
            const int d   = p / 961;
            const int rem = p - d * 961;
            const int h   = rem / 31;
            const int wx  = rem - h * 31;
            const long base = (long)n * 524288 + d * 1024 + h * 32 + wx + half;
            #pragma unroll 4
            for (int it = 0; it < 64; ++it) {
                const int c  = it >> 2;
                const int kd = (it >> 1) & 1;
                const int kh = it & 1;
                const int k  = c * 8 + kd * 4 + kh * 2 + half;
                const float v = x[base + (long)c * 32768 + kd * 1024 + kh * 32];
                const unsigned short u0 = bfbits(v);
                __nv_bfloat16_raw raw; raw.x = u0;
                const float f0 = __bfloat162float(*(__nv_bfloat16*)&raw);
                const unsigned short u1 = bfbits(v - f0);
                const int o = idx16(m, k);
                sA0[o] = u0;
                sA1[o] = u1;
                s = fmaf(v, v, s);
            }
        } else {
            #pragma unroll 4
            for (int it = 0; it < 64; ++it) {
                const int k = (it >> 2) * 8 + (((it >> 1) & 1) << 2) + ((it & 1) << 1) + half;
                const int o = idx16(m, k);
                sA0[o] = 0;
                sA1[o] = 0;
            }
        }
        ysqp[half * 128 + m] = s;
    }
    __syncthreads();
    if (tid < 128) ysq[tid] = ysqp[tid] + ysqp[128 + tid];

    // ---- per-warp fragment geometry: warp tile 32(m) x 32(n) ----
    const int m0 = (wid & 3) * 32;
    const int n0 = (wid >> 2) * 32;
    const int r    = lane & 7;
    const int midx = lane >> 3;
    const int mi1  = (midx & 1) * 8;
    const int kmi  = midx >> 1;
    const uint32_t rowA0 = (uint32_t)(m0 + mi1 + r) * 256u;   // bytes (256B rows)
    const uint32_t rowA1 = rowA0 + 16u * 256u;
    const uint32_t rowB0 = (uint32_t)(n0 + mi1 + r) * 256u;
    const uint32_t rowB1 = rowB0 + 16u * 256u;

    const int c  = lane & 3;
    const int rg = lane >> 2;

    // ---- hoisted output coordinates for this thread's 4 accumulator rows ----
    // rows: m0 + {0,8,16,24} + rg  (f in 0..1, each covering r0 and r0+8)
    long obase[4];
    bool ovalid[4];
    #pragma unroll
    for (int q = 0; q < 4; ++q) {
        const int row = row0 + m0 + q * 8 + rg;
        ovalid[q] = row < MROWS;
        if (ovalid[q]) {
            const int n = row / PVOL;
            const int p = row - n * PVOL;
            obase[q] = (long)n * D1 * PVOL + p;
        } else obase[q] = 0;
    }

    for (int iter = 0; iter < NCOL; ++iter) {
        const int col0 = iter * BN;

        // ------------- fill B (2-term bf16, STS.128) + ||w||^2 --------------
        {
            const int cg  = lane >> 2;          // 8 cols per warp
            const int sub = lane & 3;           // 32-k chunk
            const int nn  = wid * 8 + cg;       // 0..63
            const float* wr = w + (long)(col0 + nn) * KK + sub * 32;
            float s = 0.0f;
            #pragma unroll
            for (int j = 0; j < 4; ++j) {
                const float4 va = *(const float4*)(wr + j * 8);
                const float4 vb = *(const float4*)(wr + j * 8 + 4);
                const float f[8] = {va.x, va.y, va.z, va.w, vb.x, vb.y, vb.z, vb.w};
                uint32_t h[4], l[4];
                #pragma unroll
                for (int q = 0; q < 4; ++q) {
                    const unsigned short h0 = bfbits(f[2 * q]);
                    const unsigned short h1 = bfbits(f[2 * q + 1]);
                    __nv_bfloat16_raw r0; r0.x = h0;
                    __nv_bfloat16_raw r1; r1.x = h1;
                    const float g0 = __bfloat162float(*(__nv_bfloat16*)&r0);
                    const float g1 = __bfloat162float(*(__nv_bfloat16*)&r1);
                    const unsigned short l0 = bfbits(f[2 * q] - g0);
                    const unsigned short l1 = bfbits(f[2 * q + 1] - g1);
                    h[q] = (uint32_t)h0 | ((uint32_t)h1 << 16);
                    l[q] = (uint32_t)l0 | ((uint32_t)l1 << 16);
                    s = fmaf(f[2 * q], f[2 * q], s);
                    s = fmaf(f[2 * q + 1], f[2 * q + 1], s);
                }
                const int choff = ((((sub << 2) + j) ^ (nn & 7)) << 4);
                *(uint4*)(smem + O_B0 + nn * 256 + choff) = make_uint4(h[0], h[1], h[2], h[3]);
                *(uint4*)(smem + O_B1 + nn * 256 + choff) = make_uint4(l[0], l[1], l[2], l[3]);
            }
            s += __shfl_xor_sync(0xFFFFFFFFu, s, 2);
            s += __shfl_xor_sync(0xFFFFFFFFu, s, 1);
            if (sub == 0) wsq[nn] = s;
        }
        __syncthreads();

        // ------------- tensor GEMM: 3-pass bf16 m16n8k16 ---------------------
        float acc[2][4][4];
        #pragma unroll
        for (int f = 0; f < 2; ++f)
            #pragma unroll
            for (int g = 0; g < 4; ++g)
                #pragma unroll
                for (int e = 0; e < 4; ++e) acc[f][g][e] = 0.0f;

        #pragma unroll
        for (int ks = 0; ks < 8; ++ks) {
            const uint32_t choff = (uint32_t)((((ks * 2 + kmi) ^ r)) << 4);
            uint32_t A0[2][4], A1[2][4], B0[2][4], B1[2][4];
            ldsm4(A0[0][0], A0[0][1], A0[0][2], A0[0][3], aA0 + rowA0 + choff);
            ldsm4(A0[1][0], A0[1][1], A0[1][2], A0[1][3], aA0 + rowA1 + choff);
            ldsm4(A1[0][0], A1[0][1], A1[0][2], A1[0][3], aA1 + rowA0 + choff);
            ldsm4(A1[1][0], A1[1][1], A1[1][2], A1[1][3], aA1 + rowA1 + choff);
            ldsm4(B0[0][0], B0[0][1], B0[0][2], B0[0][3], aB0 + rowB0 + choff);
            ldsm4(B0[1][0], B0[1][1], B0[1][2], B0[1][3], aB0 + rowB1 + choff);
            ldsm4(B1[0][0], B1[0][1], B1[0][2], B1[0][3], aB1 + rowB0 + choff);
            ldsm4(B1[1][0], B1[1][1], B1[1][2], B1[1][3], aB1 + rowB1 + choff);

            #pragma unroll
            for (int f = 0; f < 2; ++f)
                #pragma unroll
                for (int u = 0; u < 2; ++u)
                    #pragma unroll
                    for (int v = 0; v < 2; ++v) {
                        float* ac = acc[f][u * 2 + v];
                        mma_bf16(ac, A0[f], B0[u][v], B0[u][2 + v]);
                        mma_bf16(ac, A0[f], B1[u][v], B1[u][2 + v]);
                        mma_bf16(ac, A1[f], B0[u][v], B0[u][2 + v]);
                        // A1*B1 dropped: |a1*b1| <= 2^-18 |y||w| — negligible
                    }
        }

        // ------------- epilogue: exp + DIRECT global stores -------------------
        #pragma unroll
        for (int f = 0; f < 2; ++f) {
            const int q0 = f * 2;              // row index m0 + q*8 + rg
            const int q1 = f * 2 + 1;
            const float ys0 = ysq[m0 + q0 * 8 + rg];
            const float ys1 = ysq[m0 + q1 * 8 + rg];
            #pragma unroll
            for (int u = 0; u < 2; ++u)
                #pragma unroll
                for (int v = 0; v < 2; ++v) {
                    const float* ac = acc[f][u * 2 + v];
                    const int cb = n0 + u * 16 + v * 8 + 2 * c;
                    const float ws0 = wsq[cb];
                    const float ws1 = wsq[cb + 1];
                    const long co0 = (long)(col0 + cb) * PVOL;
                    const long co1 = co0 + PVOL;
                    if (ovalid[q0]) {
                        out[obase[q0] + co0] = __expf(fmaf(2.0f, ac[0], -(ys0 + ws0)));
                        out[obase[q0] + co1] = __expf(fmaf(2.0f, ac[1], -(ys0 + ws1)));
                    }
                    if (ovalid[q1]) {
                        out[obase[q1] + co0] = __expf(fmaf(2.0f, ac[2], -(ys1 + ws0)));
                        out[obase[q1] + co1] = __expf(fmaf(2.0f, ac[3], -(ys1 + ws1)));
                    }
                }
        }
        __syncthreads();   // all B reads done before next fill overwrites
    }
}

extern "C" void kernel_launch(void* const* d_in, const int* in_sizes, int n_in,
                              void* d_out, int out_size) {
    const float* x = (const float*)d_in[0];
    const float* w = (const float*)d_in[1];
    float* out = (float*)d_out;

    cudaFuncSetAttribute(gk_kernel, cudaFuncAttributeMaxDynamicSharedMemorySize,
                         SMEM_BYTES);
    dim3 grid((MROWS + BM - 1) / BM, 1);   // 931
    gk_kernel<<<grid, NT, SMEM_BYTES>>>(x, w, out);
}